// round 9
// baseline (speedup 1.0000x reference)
#include <cuda_runtime.h>
#include <cuda_fp16.h>
#include <math.h>

#define B_   4
#define CIN  32
#define HID  32
#define T_   31
#define H_   96
#define W_   96
#define HW   (H_*W_)          /* 9216 */
#define CTHW ((size_t)T_*HW)  /* per-channel stride 285696 */
#define NELEM (B_*HID*T_*HW)
#define NPIX  (B_*4*T_*H_*W_) /* b,cig,t,h,w = 4,571,136 */

// Scratch (device globals; no runtime allocation)
__device__ float g_Z[NELEM];                // tanh gate   [B][C][T][H][W]
__device__ float g_F[NELEM];                // sigmoid gate[B][C][T][H][W]
__device__ uint4 g_x[NPIX];                 // input fp16: pixel = 8 ci (4 fp16x2)
__device__ unsigned g_wfrag[4*14*4*32*4];   // fp16 weight fragments (2 nt / uint4)

// ---------------------------------------------------------------------------
// f32x2 packed-FMA helpers (Blackwell)
// ---------------------------------------------------------------------------
__device__ __forceinline__ unsigned long long ffma2(unsigned long long a,
                                                    unsigned long long b,
                                                    unsigned long long c) {
    unsigned long long d;
    asm("fma.rn.f32x2 %0, %1, %2, %3;" : "=l"(d) : "l"(a), "l"(b), "l"(c));
    return d;
}
__device__ __forceinline__ unsigned long long pack2(float lo, float hi) {
    unsigned long long r;
    asm("mov.b64 %0, {%1, %2};" : "=l"(r) : "f"(lo), "f"(hi));
    return r;
}
__device__ __forceinline__ void unpack2(unsigned long long v, float &lo, float &hi) {
    asm("mov.b64 {%0, %1}, %2;" : "=f"(lo), "=f"(hi) : "l"(v));
}

// cp.async 16B with zero-fill when pred==false (src-size=0 -> no global read)
__device__ __forceinline__ void cp16(unsigned* sdst, const void* gsrc, bool pred) {
    unsigned saddr = (unsigned)__cvta_generic_to_shared(sdst);
    int sb = pred ? 16 : 0;
    asm volatile("cp.async.cg.shared.global [%0], [%1], 16, %2;\n"
                 :: "r"(saddr), "l"(gsrc), "r"(sb) : "memory");
}

// ---------------------------------------------------------------------------
// Input prep: fp32 -> fp16x2, pixel = 8 ci packed into one uint4.
// ---------------------------------------------------------------------------
__global__ void xsplit_kernel(const float* __restrict__ in) {
    int idx = blockIdx.x * 256 + threadIdx.x;
    if (idx >= NPIX) return;
    int w = idx % W_; int r = idx / W_;
    int h = r % H_;   r /= H_;
    int t = r % T_;   r /= T_;
    int cig = r & 3;  int b = r >> 2;
    size_t base = ((size_t)((b*CIN + cig*8)*T_ + t)*H_ + h)*W_ + w;
    unsigned wds[4];
    #pragma unroll
    for (int j = 0; j < 4; j++) {
        __half h0 = __float2half_rn(in[base + (size_t)(2*j)*CTHW]);
        __half h1 = __float2half_rn(in[base + (size_t)(2*j+1)*CTHW]);
        wds[j] = (unsigned)__half_as_ushort(h0) | ((unsigned)__half_as_ushort(h1) << 16);
    }
    g_x[idx] = make_uint4(wds[0], wds[1], wds[2], wds[3]);
}

// ---------------------------------------------------------------------------
// Weight fragment prep (fp16). word idx = cig*7168 + s*512 + ntp*128 + lane*4 + j
// ---------------------------------------------------------------------------
__global__ void wfrag_kernel(const float* __restrict__ w) {
    int idx = blockIdx.x * 256 + threadIdx.x;
    if (idx >= 4*7168) return;
    int j    = idx & 3;
    int lane = (idx >> 2) & 31;
    int ntp  = (idx >> 7) & 3;
    int rest = idx >> 9;
    int s    = rest % 14;
    int cig  = rest / 14;
    int nt = ntp*2 + (j >> 1);
    int r  = j & 1;
    int q  = lane & 3;
    int n  = nt*8 + (lane >> 2);    // co
    unsigned word = 0;
    for (int e = 0; e < 2; e++) {
        int k   = s*16 + q*2 + r*8 + e;
        int cil = k & 7;
        int tap = k >> 3;
        float val = 0.f;
        if (tap < 27) val = w[(n*CIN + (cig*8 + cil))*27 + tap];
        word |= ((unsigned)__half_as_ushort(__float2half_rn(val))) << (16*e);
    }
    g_wfrag[idx] = word;
}

// ---------------------------------------------------------------------------
__device__ __forceinline__ void mma16816(float (&c)[4], const unsigned (&a)[4],
                                         const unsigned b0, const unsigned b1) {
    asm volatile(
        "mma.sync.aligned.m16n8k16.row.col.f32.f16.f16.f32 "
        "{%0,%1,%2,%3}, {%4,%5,%6,%7}, {%8,%9}, {%0,%1,%2,%3};\n"
        : "+f"(c[0]), "+f"(c[1]), "+f"(c[2]), "+f"(c[3])
        : "r"(a[0]), "r"(a[1]), "r"(a[2]), "r"(a[3]), "r"(b0), "r"(b1));
}

// ---------------------------------------------------------------------------
// Conv3d 3x3x3 SAME + bias + tanh/sigmoid via implicit-GEMM HMMA (fp16, fp32
// accumulate), double-buffered cp.async pipeline. UNCHANGED from R8.
// ---------------------------------------------------------------------------
#define SX_WORDS (3*10*34*4)        /* 4080 words */
#define SWF_WORDS 7168
#define STAGE_WORDS (SX_WORDS + SWF_WORDS)
#define CONV_SMEM (2*STAGE_WORDS*4) /* 89,984 bytes */

__global__ __launch_bounds__(256, 2)
void conv_kernel(const float* __restrict__ bias) {
    extern __shared__ unsigned smw[];

    const int w0 = blockIdx.x * 32;
    const int h0 = blockIdx.y * 8;
    const int bz = blockIdx.z;
    const int b  = bz / T_;
    const int t  = bz % T_;
    const int tid  = threadIdx.x;
    const int lane = tid & 31;
    const int wi   = tid >> 5;      // warp -> output row
    const int g2   = lane >> 2;     // m-row within tile
    const int q2   = lane & 3;      // k / n low bits

    float acc[2][8][4];
    #pragma unroll
    for (int a2 = 0; a2 < 2; a2++)
        #pragma unroll
        for (int nt = 0; nt < 8; nt++)
            #pragma unroll
            for (int r = 0; r < 4; r++) acc[a2][nt][r] = 0.f;

    auto issue_load = [&](int cig, unsigned* s_x, unsigned* s_wf) {
        #pragma unroll
        for (int e0 = 0; e0 < 4; e0++) {
            int e = tid + e0*256;
            if (e < 1020) {
                int x  = e % 34; int r2 = e / 34;
                int y  = r2 % 10; int tz = r2 / 10;
                int tt = t + tz - 1, gh = h0 + y - 1, gw = w0 + x - 1;
                bool ok = (tt >= 0) & (tt < T_) & (gh >= 0) & (gh < H_) &
                          (gw >= 0) & (gw < W_);
                size_t gi = ok ? (((size_t)((b*4 + cig)*T_ + tt)*H_ + gh)*W_ + gw) : 0;
                cp16(s_x + e*4, g_x + gi, ok);
            }
        }
        const uint4* src = (const uint4*)(g_wfrag + cig*SWF_WORDS);
        #pragma unroll
        for (int li0 = 0; li0 < 7; li0++) {
            int li = tid + li0*256;
            cp16(s_wf + li*4, src + li, true);
        }
        asm volatile("cp.async.commit_group;\n" ::: "memory");
    };

    issue_load(0, smw, smw + SX_WORDS);

    for (int cig = 0; cig < 4; cig++) {
        unsigned* s_x  = smw + (cig & 1)*STAGE_WORDS;
        unsigned* s_wf = s_x + SX_WORDS;
        if (cig < 3) {
            unsigned* n_x = smw + ((cig + 1) & 1)*STAGE_WORDS;
            issue_load(cig + 1, n_x, n_x + SX_WORDS);
            asm volatile("cp.async.wait_group 1;\n" ::: "memory");
        } else {
            asm volatile("cp.async.wait_group 0;\n" ::: "memory");
        }
        __syncthreads();

        #pragma unroll
        for (int s = 0; s < 14; s++) {
            const int tapA = 2*s, tapB = 2*s + 1;
            const int ktA = tapA/9, rA = tapA%9, khA = rA/3, kwA = rA%3;
            const bool zB = (tapB == 27);
            const int ktB = zB ? 0 : tapB/9;
            const int rB  = zB ? 0 : tapB%9;
            const int khB = rB/3, kwB = rB%3;
            const int yA = wi + khA, yB = wi + khB;

            unsigned A[2][4];
            #pragma unroll
            for (int a2 = 0; a2 < 2; a2++) {
                const int xb = a2*16 + g2;
                const int iA0 = (((ktA*10 + yA)*34 + xb + kwA)*4) + q2;
                A[a2][0] = s_x[iA0];
                A[a2][1] = s_x[iA0 + 32];           /* +8 pixels */
                if (!zB) {
                    const int iB0 = (((ktB*10 + yB)*34 + xb + kwB)*4) + q2;
                    A[a2][2] = s_x[iB0];
                    A[a2][3] = s_x[iB0 + 32];       /* +8 pixels */
                } else {
                    A[a2][2] = 0u; A[a2][3] = 0u;
                }
            }
            #pragma unroll
            for (int ntp = 0; ntp < 4; ntp++) {
                uint4 B4 = *(const uint4*)(s_wf + (s*4 + ntp)*128 + lane*4);
                mma16816(acc[0][2*ntp],   A[0], B4.x, B4.y);
                mma16816(acc[1][2*ntp],   A[1], B4.x, B4.y);
                mma16816(acc[0][2*ntp+1], A[0], B4.z, B4.w);
                mma16816(acc[1][2*ntp+1], A[1], B4.z, B4.w);
            }
        }
        __syncthreads();
    }

    const int h = h0 + wi;
    #pragma unroll
    for (int a2 = 0; a2 < 2; a2++) {
        const int wbase = w0 + a2*16 + g2;
        #pragma unroll
        for (int nt = 0; nt < 8; nt++) {
            const int co = nt*8 + q2*2;
            const float b0v = __ldg(bias + co), b1v = __ldg(bias + co + 1);
            float x00 = acc[a2][nt][0] + b0v;
            float x01 = acc[a2][nt][1] + b1v;
            float x10 = acc[a2][nt][2] + b0v;
            float x11 = acc[a2][nt][3] + b1v;
            float y00, y01, y10, y11;
            float* dst; int c_;
            if (nt < 4) {
                y00 = tanhf(x00); y01 = tanhf(x01); y10 = tanhf(x10); y11 = tanhf(x11);
                dst = g_Z; c_ = co;
            } else {
                y00 = 1.f/(1.f + __expf(-x00)); y01 = 1.f/(1.f + __expf(-x01));
                y10 = 1.f/(1.f + __expf(-x10)); y11 = 1.f/(1.f + __expf(-x11));
                dst = g_F; c_ = co - HID;
            }
            size_t base0 = ((size_t)((b*HID + c_)*T_ + t)*H_ + h)*W_ + wbase;
            dst[base0]     = y00; dst[base0 + 8] = y10;
            size_t base1 = base0 + CTHW;
            dst[base1]     = y01; dst[base1 + 8] = y11;
        }
    }
}

// ---------------------------------------------------------------------------
// Fused recurrence + channel attention — low-register f32x2 edition.
// 16 pixels/block, 3 blocks/SM (24 warps). Phase 2 keeps only a2[32] (64 regs)
// live: scores and ah both stream t-pairs from smem. In-place ah write is
// protected by one __syncwarp per t-pair (column tp reads precede its write).
// ---------------------------------------------------------------------------
#define RS   34
#define PS   1090
#define ATTN_SMEM (16*PS*4)

__global__ __launch_bounds__(256, 3)
void attn_kernel(const float* __restrict__ gamma, float* __restrict__ out) {
    extern __shared__ float sq[];    // [16][1090]
    const int w0 = blockIdx.x * 16;
    const int h  = blockIdx.y;
    const int b  = blockIdx.z;
    const int tid = threadIdx.x;

    // ---- phase 1: recurrence ----
    {
        const int px  = tid & 15;
        const int c16 = tid >> 4;
        #pragma unroll
        for (int ch = 0; ch < 2; ch++) {
            const int c = ch*16 + c16;
            size_t base = (size_t)((b*HID + c)*T_)*HW + (size_t)h*W_ + w0 + px;
            float hs = 0.f;
            float* dst = sq + px*PS + c*RS;
            #pragma unroll
            for (int t = 0; t < T_; t++) {
                float z = g_Z[base + (size_t)t*HW];
                float f = g_F[base + (size_t)t*HW];
                hs = f*hs + (1.f - f)*z;
                dst[t] = hs;
            }
            dst[31] = 0.f;   // pad slot read by float2 pair (30,31)
        }
    }
    __syncthreads();

    // ---- phase 2: attention ----
    const float gam = __ldg(gamma);
    const int lane = tid & 31;
    const int wid  = tid >> 5;

    for (int it = 0; it < 2; it++) {
        float* q = sq + (wid*2 + it)*PS;

        // scores: a2[d] accumulates (lo,hi) partial dot of row_lane x row_d
        unsigned long long a2[32];
        #pragma unroll
        for (int d = 0; d < 32; d++) a2[d] = 0ULL;

        #pragma unroll 2
        for (int tp = 0; tp < 16; tp++) {
            unsigned long long qt2 = *(const unsigned long long*)&q[lane*RS + 2*tp];
            #pragma unroll
            for (int d = 0; d < 32; d++)
                a2[d] = ffma2(*(const unsigned long long*)&q[d*RS + 2*tp], qt2, a2[d]);
        }

        float a[32];
        #pragma unroll
        for (int d = 0; d < 32; d++) {
            float lo, hi; unpack2(a2[d], lo, hi);
            a[d] = lo + hi;
        }

        // own-row stats == column stats (Gram symmetry)
        float m = a[0];
        #pragma unroll
        for (int d = 1; d < 32; d++) m = fmaxf(m, a[d]);
        float ssum = 0.f;
        #pragma unroll
        for (int d = 0; d < 32; d++) ssum += __expf(a[d] - m);

        #pragma unroll
        for (int d = 0; d < 32; d++) {
            float mc  = __shfl_sync(0xffffffffu, m,    d);
            float sc2 = __shfl_sync(0xffffffffu, ssum, d);
            float av  = __expf(a[d] - mc) * (0.17677669529663687f / sc2); // /sqrt(32)
            a2[d] = pack2(av, av);
        }

        // ah: t-pair outer, in-place update with per-tp syncwarp
        #pragma unroll 2
        for (int tp = 0; tp < 16; tp++) {
            unsigned long long acc2 = 0ULL;
            #pragma unroll
            for (int d = 0; d < 32; d++)
                acc2 = ffma2(*(const unsigned long long*)&q[d*RS + 2*tp], a2[d], acc2);
            float lo, hi; unpack2(acc2, lo, hi);
            float2 own = *(float2*)&q[lane*RS + 2*tp];
            own.x = fmaf(gam, lo, own.x);
            own.y = fmaf(gam, hi, own.y);
            __syncwarp();                           // all column-tp reads done
            *(float2*)&q[lane*RS + 2*tp] = own;     // slot 31 garbage, never read
        }
        __syncwarp();
    }
    __syncthreads();

    // ---- phase 3: coalesced store to [B][C][T][H][W] ----
    for (int i = tid; i < 16*992; i += 256) {
        int wpx = i & 15;
        int ct  = i >> 4;
        int c   = ct / 31;
        int t2  = ct - c*31;
        out[((size_t)((b*HID + c)*T_ + t2)*H_ + h)*W_ + w0 + wpx] =
            sq[wpx*PS + c*RS + t2];
    }
}

// ---------------------------------------------------------------------------
extern "C" void kernel_launch(void* const* d_in, const int* in_sizes, int n_in,
                              void* d_out, int out_size) {
    const float* input  = (const float*)d_in[0];
    const float* conv_w = (const float*)d_in[1];
    const float* conv_b = (const float*)d_in[2];
    const float* gamma  = (const float*)d_in[3];
    float* out = (float*)d_out;

    xsplit_kernel<<<(NPIX + 255)/256, 256>>>(input);           // our idx 0
    wfrag_kernel<<<(4*7168 + 255)/256, 256>>>(conv_w);         // our idx 1

    cudaFuncSetAttribute(conv_kernel, cudaFuncAttributeMaxDynamicSharedMemorySize,
                         CONV_SMEM);
    dim3 cgrid(W_/32, H_/8, B_*T_);
    conv_kernel<<<cgrid, 256, CONV_SMEM>>>(conv_b);            // our idx 2

    cudaFuncSetAttribute(attn_kernel, cudaFuncAttributeMaxDynamicSharedMemorySize,
                         ATTN_SMEM);
    dim3 agrid(W_/16, H_, B_);
    attn_kernel<<<agrid, 256, ATTN_SMEM>>>(gamma, out);        // our idx 3 -> ncu
}

// round 10
// speedup vs baseline: 1.0095x; 1.0095x over previous
#include <cuda_runtime.h>
#include <cuda_fp16.h>
#include <math.h>

#define B_   4
#define CIN  32
#define HID  32
#define T_   31
#define H_   96
#define W_   96
#define HW   (H_*W_)          /* 9216 */
#define CTHW ((size_t)T_*HW)  /* per-channel stride 285696 */
#define NELEM (B_*HID*T_*HW)
#define NPIX  (B_*4*T_*H_*W_) /* b,cig,t,h,w = 4,571,136 */

// Scratch (device globals; no runtime allocation)
__device__ float g_Z[NELEM];                // tanh gate   [B][C][T][H][W]
__device__ float g_F[NELEM];                // sigmoid gate[B][C][T][H][W]
__device__ uint4 g_x[NPIX];                 // input fp16: pixel = 8 ci (4 fp16x2)
__device__ unsigned g_wfrag[4*14*4*32*4];   // fp16 weight fragments (2 nt / uint4)

// ---------------------------------------------------------------------------
// f32x2 packed-FMA helpers (Blackwell)
// ---------------------------------------------------------------------------
__device__ __forceinline__ unsigned long long ffma2(unsigned long long a,
                                                    unsigned long long b,
                                                    unsigned long long c) {
    unsigned long long d;
    asm("fma.rn.f32x2 %0, %1, %2, %3;" : "=l"(d) : "l"(a), "l"(b), "l"(c));
    return d;
}
__device__ __forceinline__ unsigned long long pack2(float lo, float hi) {
    unsigned long long r;
    asm("mov.b64 %0, {%1, %2};" : "=l"(r) : "f"(lo), "f"(hi));
    return r;
}
__device__ __forceinline__ void unpack2(unsigned long long v, float &lo, float &hi) {
    asm("mov.b64 {%0, %1}, %2;" : "=f"(lo), "=f"(hi) : "l"(v));
}

// cp.async 16B with zero-fill when pred==false (src-size=0 -> no global read)
__device__ __forceinline__ void cp16(unsigned* sdst, const void* gsrc, bool pred) {
    unsigned saddr = (unsigned)__cvta_generic_to_shared(sdst);
    int sb = pred ? 16 : 0;
    asm volatile("cp.async.cg.shared.global [%0], [%1], 16, %2;\n"
                 :: "r"(saddr), "l"(gsrc), "r"(sb) : "memory");
}

// ---------------------------------------------------------------------------
// Input prep: fp32 -> fp16x2, pixel = 8 ci packed into one uint4.
// ---------------------------------------------------------------------------
__global__ void xsplit_kernel(const float* __restrict__ in) {
    int idx = blockIdx.x * 256 + threadIdx.x;
    if (idx >= NPIX) return;
    int w = idx % W_; int r = idx / W_;
    int h = r % H_;   r /= H_;
    int t = r % T_;   r /= T_;
    int cig = r & 3;  int b = r >> 2;
    size_t base = ((size_t)((b*CIN + cig*8)*T_ + t)*H_ + h)*W_ + w;
    unsigned wds[4];
    #pragma unroll
    for (int j = 0; j < 4; j++) {
        __half h0 = __float2half_rn(in[base + (size_t)(2*j)*CTHW]);
        __half h1 = __float2half_rn(in[base + (size_t)(2*j+1)*CTHW]);
        wds[j] = (unsigned)__half_as_ushort(h0) | ((unsigned)__half_as_ushort(h1) << 16);
    }
    g_x[idx] = make_uint4(wds[0], wds[1], wds[2], wds[3]);
}

// ---------------------------------------------------------------------------
// Weight fragment prep (fp16). word idx = cig*7168 + s*512 + ntp*128 + lane*4 + j
// ---------------------------------------------------------------------------
__global__ void wfrag_kernel(const float* __restrict__ w) {
    int idx = blockIdx.x * 256 + threadIdx.x;
    if (idx >= 4*7168) return;
    int j    = idx & 3;
    int lane = (idx >> 2) & 31;
    int ntp  = (idx >> 7) & 3;
    int rest = idx >> 9;
    int s    = rest % 14;
    int cig  = rest / 14;
    int nt = ntp*2 + (j >> 1);
    int r  = j & 1;
    int q  = lane & 3;
    int n  = nt*8 + (lane >> 2);    // co
    unsigned word = 0;
    for (int e = 0; e < 2; e++) {
        int k   = s*16 + q*2 + r*8 + e;
        int cil = k & 7;
        int tap = k >> 3;
        float val = 0.f;
        if (tap < 27) val = w[(n*CIN + (cig*8 + cil))*27 + tap];
        word |= ((unsigned)__half_as_ushort(__float2half_rn(val))) << (16*e);
    }
    g_wfrag[idx] = word;
}

// ---------------------------------------------------------------------------
__device__ __forceinline__ void mma16816(float (&c)[4], const unsigned (&a)[4],
                                         const unsigned b0, const unsigned b1) {
    asm volatile(
        "mma.sync.aligned.m16n8k16.row.col.f32.f16.f16.f32 "
        "{%0,%1,%2,%3}, {%4,%5,%6,%7}, {%8,%9}, {%0,%1,%2,%3};\n"
        : "+f"(c[0]), "+f"(c[1]), "+f"(c[2]), "+f"(c[3])
        : "r"(a[0]), "r"(a[1]), "r"(a[2]), "r"(a[3]), "r"(b0), "r"(b1));
}

// ---------------------------------------------------------------------------
// Conv3d 3x3x3 SAME + bias + tanh/sigmoid via implicit-GEMM HMMA (fp16, fp32
// accumulate), double-buffered cp.async pipeline. UNCHANGED from R8.
// ---------------------------------------------------------------------------
#define SX_WORDS (3*10*34*4)        /* 4080 words */
#define SWF_WORDS 7168
#define STAGE_WORDS (SX_WORDS + SWF_WORDS)
#define CONV_SMEM (2*STAGE_WORDS*4) /* 89,984 bytes */

__global__ __launch_bounds__(256, 2)
void conv_kernel(const float* __restrict__ bias) {
    extern __shared__ unsigned smw[];

    const int w0 = blockIdx.x * 32;
    const int h0 = blockIdx.y * 8;
    const int bz = blockIdx.z;
    const int b  = bz / T_;
    const int t  = bz % T_;
    const int tid  = threadIdx.x;
    const int lane = tid & 31;
    const int wi   = tid >> 5;      // warp -> output row
    const int g2   = lane >> 2;     // m-row within tile
    const int q2   = lane & 3;      // k / n low bits

    float acc[2][8][4];
    #pragma unroll
    for (int a2 = 0; a2 < 2; a2++)
        #pragma unroll
        for (int nt = 0; nt < 8; nt++)
            #pragma unroll
            for (int r = 0; r < 4; r++) acc[a2][nt][r] = 0.f;

    auto issue_load = [&](int cig, unsigned* s_x, unsigned* s_wf) {
        #pragma unroll
        for (int e0 = 0; e0 < 4; e0++) {
            int e = tid + e0*256;
            if (e < 1020) {
                int x  = e % 34; int r2 = e / 34;
                int y  = r2 % 10; int tz = r2 / 10;
                int tt = t + tz - 1, gh = h0 + y - 1, gw = w0 + x - 1;
                bool ok = (tt >= 0) & (tt < T_) & (gh >= 0) & (gh < H_) &
                          (gw >= 0) & (gw < W_);
                size_t gi = ok ? (((size_t)((b*4 + cig)*T_ + tt)*H_ + gh)*W_ + gw) : 0;
                cp16(s_x + e*4, g_x + gi, ok);
            }
        }
        const uint4* src = (const uint4*)(g_wfrag + cig*SWF_WORDS);
        #pragma unroll
        for (int li0 = 0; li0 < 7; li0++) {
            int li = tid + li0*256;
            cp16(s_wf + li*4, src + li, true);
        }
        asm volatile("cp.async.commit_group;\n" ::: "memory");
    };

    issue_load(0, smw, smw + SX_WORDS);

    for (int cig = 0; cig < 4; cig++) {
        unsigned* s_x  = smw + (cig & 1)*STAGE_WORDS;
        unsigned* s_wf = s_x + SX_WORDS;
        if (cig < 3) {
            unsigned* n_x = smw + ((cig + 1) & 1)*STAGE_WORDS;
            issue_load(cig + 1, n_x, n_x + SX_WORDS);
            asm volatile("cp.async.wait_group 1;\n" ::: "memory");
        } else {
            asm volatile("cp.async.wait_group 0;\n" ::: "memory");
        }
        __syncthreads();

        #pragma unroll
        for (int s = 0; s < 14; s++) {
            const int tapA = 2*s, tapB = 2*s + 1;
            const int ktA = tapA/9, rA = tapA%9, khA = rA/3, kwA = rA%3;
            const bool zB = (tapB == 27);
            const int ktB = zB ? 0 : tapB/9;
            const int rB  = zB ? 0 : tapB%9;
            const int khB = rB/3, kwB = rB%3;
            const int yA = wi + khA, yB = wi + khB;

            unsigned A[2][4];
            #pragma unroll
            for (int a2 = 0; a2 < 2; a2++) {
                const int xb = a2*16 + g2;
                const int iA0 = (((ktA*10 + yA)*34 + xb + kwA)*4) + q2;
                A[a2][0] = s_x[iA0];
                A[a2][1] = s_x[iA0 + 32];           /* +8 pixels */
                if (!zB) {
                    const int iB0 = (((ktB*10 + yB)*34 + xb + kwB)*4) + q2;
                    A[a2][2] = s_x[iB0];
                    A[a2][3] = s_x[iB0 + 32];       /* +8 pixels */
                } else {
                    A[a2][2] = 0u; A[a2][3] = 0u;
                }
            }
            #pragma unroll
            for (int ntp = 0; ntp < 4; ntp++) {
                uint4 B4 = *(const uint4*)(s_wf + (s*4 + ntp)*128 + lane*4);
                mma16816(acc[0][2*ntp],   A[0], B4.x, B4.y);
                mma16816(acc[1][2*ntp],   A[1], B4.x, B4.y);
                mma16816(acc[0][2*ntp+1], A[0], B4.z, B4.w);
                mma16816(acc[1][2*ntp+1], A[1], B4.z, B4.w);
            }
        }
        __syncthreads();
    }

    const int h = h0 + wi;
    #pragma unroll
    for (int a2 = 0; a2 < 2; a2++) {
        const int wbase = w0 + a2*16 + g2;
        #pragma unroll
        for (int nt = 0; nt < 8; nt++) {
            const int co = nt*8 + q2*2;
            const float b0v = __ldg(bias + co), b1v = __ldg(bias + co + 1);
            float x00 = acc[a2][nt][0] + b0v;
            float x01 = acc[a2][nt][1] + b1v;
            float x10 = acc[a2][nt][2] + b0v;
            float x11 = acc[a2][nt][3] + b1v;
            float y00, y01, y10, y11;
            float* dst; int c_;
            if (nt < 4) {
                y00 = tanhf(x00); y01 = tanhf(x01); y10 = tanhf(x10); y11 = tanhf(x11);
                dst = g_Z; c_ = co;
            } else {
                y00 = 1.f/(1.f + __expf(-x00)); y01 = 1.f/(1.f + __expf(-x01));
                y10 = 1.f/(1.f + __expf(-x10)); y11 = 1.f/(1.f + __expf(-x11));
                dst = g_F; c_ = co - HID;
            }
            size_t base0 = ((size_t)((b*HID + c_)*T_ + t)*H_ + h)*W_ + wbase;
            dst[base0]     = y00; dst[base0 + 8] = y10;
            size_t base1 = base0 + CTHW;
            dst[base1]     = y01; dst[base1 + 8] = y11;
        }
    }
}

// ---------------------------------------------------------------------------
// Fused recurrence + channel attention — LDS.128 edition.
// RS=36 floats (144 B: every row 16B-aligned), PS=1156 (16B-aligned pixels).
// Phase 2: rows stream as 8 broadcast LDS.128 each (was 16 LDS.64) — halves
// shared-pipe transactions. qr released after scores; own row reloaded at
// writeback so peak regs ~= a[32]+ahp[16ull] -> 3 blocks/SM.
// ---------------------------------------------------------------------------
#define RS   36
#define PS   1156
#define ATTN_SMEM (16*PS*4)   /* 73,984 B */

__global__ __launch_bounds__(256, 3)
void attn_kernel(const float* __restrict__ gamma, float* __restrict__ out) {
    extern __shared__ float sq[];    // [16][1156]
    const int w0 = blockIdx.x * 16;
    const int h  = blockIdx.y;
    const int b  = blockIdx.z;
    const int tid = threadIdx.x;

    // ---- phase 1: recurrence ----
    {
        const int px  = tid & 15;
        const int c16 = tid >> 4;
        #pragma unroll
        for (int ch = 0; ch < 2; ch++) {
            const int c = ch*16 + c16;
            size_t base = (size_t)((b*HID + c)*T_)*HW + (size_t)h*W_ + w0 + px;
            float hs = 0.f;
            float* dst = sq + px*PS + c*RS;
            #pragma unroll
            for (int t = 0; t < T_; t++) {
                float z = g_Z[base + (size_t)t*HW];
                float f = g_F[base + (size_t)t*HW];
                hs = f*hs + (1.f - f)*z;
                dst[t] = hs;
            }
            dst[31] = 0.f;   // pad slot read by packed pairs
        }
    }
    __syncthreads();

    // ---- phase 2: attention ----
    const float gam = __ldg(gamma);
    const int lane = tid & 31;
    const int wid  = tid >> 5;

    for (int it = 0; it < 2; it++) {
        float* q = sq + (wid*2 + it)*PS;

        float a[32];
        {
            // own row -> registers (8 LDS.128, conflict-free)
            unsigned long long qr[16];
            #pragma unroll
            for (int j = 0; j < 8; j++) {
                ulonglong2 v = *(const ulonglong2*)&q[lane*RS + 4*j];
                qr[2*j] = v.x; qr[2*j+1] = v.y;
            }
            // scores: a[d] = dot(row_lane, row_d); rows stream as LDS.128
            #pragma unroll 2
            for (int d = 0; d < 32; d++) {
                const float* row = q + d*RS;
                unsigned long long accA = 0ULL, accB = 0ULL;
                #pragma unroll
                for (int j = 0; j < 8; j++) {
                    ulonglong2 rv = *(const ulonglong2*)&row[4*j];
                    accA = ffma2(rv.x, qr[2*j],   accA);
                    accB = ffma2(rv.y, qr[2*j+1], accB);
                }
                float l0, h0, l1, h1;
                unpack2(accA, l0, h0); unpack2(accB, l1, h1);
                a[d] = (l0 + h0) + (l1 + h1);
            }
        }

        // own-row stats == column stats (Gram symmetry)
        float m = a[0];
        #pragma unroll
        for (int d = 1; d < 32; d++) m = fmaxf(m, a[d]);
        float ssum = 0.f;
        #pragma unroll
        for (int d = 0; d < 32; d++) ssum += __expf(a[d] - m);

        #pragma unroll
        for (int d = 0; d < 32; d++) {
            float mc  = __shfl_sync(0xffffffffu, m,    d);
            float sc2 = __shfl_sync(0xffffffffu, ssum, d);
            a[d] = __expf(a[d] - mc) * (0.17677669529663687f / sc2); // /sqrt(32)
        }

        // ah[t] = sum_d a[d] * q[d][t]
        unsigned long long ahp[16];
        #pragma unroll
        for (int j = 0; j < 16; j++) ahp[j] = 0ULL;
        #pragma unroll 2
        for (int d = 0; d < 32; d++) {
            unsigned long long ad2 = pack2(a[d], a[d]);
            const float* row = q + d*RS;
            #pragma unroll
            for (int j = 0; j < 8; j++) {
                ulonglong2 rv = *(const ulonglong2*)&row[4*j];
                ahp[2*j]   = ffma2(rv.x, ad2, ahp[2*j]);
                ahp[2*j+1] = ffma2(rv.y, ad2, ahp[2*j+1]);
            }
        }

        __syncwarp();    // all lanes done reading every row
        #pragma unroll
        for (int j = 0; j < 8; j++) {
            ulonglong2 ov = *(const ulonglong2*)&q[lane*RS + 4*j];  // own row reload
            float o0, o1, o2, o3, a0, a1, a2v, a3;
            unpack2(ov.x, o0, o1); unpack2(ov.y, o2, o3);
            unpack2(ahp[2*j], a0, a1); unpack2(ahp[2*j+1], a2v, a3);
            float4 res;
            res.x = fmaf(gam, a0, o0);
            res.y = fmaf(gam, a1, o1);
            res.z = fmaf(gam, a2v, o2);
            res.w = fmaf(gam, a3, o3);
            *(float4*)&q[lane*RS + 4*j] = res;   // slot 31 stays 0 (both terms 0)
        }
        __syncwarp();
    }
    __syncthreads();

    // ---- phase 3: coalesced store to [B][C][T][H][W] ----
    for (int i = tid; i < 16*992; i += 256) {
        int wpx = i & 15;
        int ct  = i >> 4;
        int c   = ct / 31;
        int t2  = ct - c*31;
        out[((size_t)((b*HID + c)*T_ + t2)*H_ + h)*W_ + w0 + wpx] =
            sq[wpx*PS + c*RS + t2];
    }
}

// ---------------------------------------------------------------------------
extern "C" void kernel_launch(void* const* d_in, const int* in_sizes, int n_in,
                              void* d_out, int out_size) {
    const float* input  = (const float*)d_in[0];
    const float* conv_w = (const float*)d_in[1];
    const float* conv_b = (const float*)d_in[2];
    const float* gamma  = (const float*)d_in[3];
    float* out = (float*)d_out;

    xsplit_kernel<<<(NPIX + 255)/256, 256>>>(input);           // our idx 0
    wfrag_kernel<<<(4*7168 + 255)/256, 256>>>(conv_w);         // our idx 1

    cudaFuncSetAttribute(conv_kernel, cudaFuncAttributeMaxDynamicSharedMemorySize,
                         CONV_SMEM);
    dim3 cgrid(W_/32, H_/8, B_*T_);
    conv_kernel<<<cgrid, 256, CONV_SMEM>>>(conv_b);            // our idx 2

    cudaFuncSetAttribute(attn_kernel, cudaFuncAttributeMaxDynamicSharedMemorySize,
                         ATTN_SMEM);
    dim3 agrid(W_/16, H_, B_);
    attn_kernel<<<agrid, 256, ATTN_SMEM>>>(gamma, out);        // our idx 3 -> ncu
}

// round 12
// speedup vs baseline: 1.1215x; 1.1109x over previous
#include <cuda_runtime.h>
#include <cuda_fp16.h>
#include <math.h>

#define B_   4
#define CIN  32
#define HID  32
#define T_   31
#define H_   96
#define W_   96
#define HW   (H_*W_)          /* 9216 */
#define CTHW ((size_t)T_*HW)  /* per-channel stride 285696 */
#define NELEM (B_*HID*T_*HW)
#define NPIX  (B_*4*T_*H_*W_) /* b,cig,t,h,w = 4,571,136 */

// Scratch (device globals; no runtime allocation)
__device__ float g_Z[NELEM];                // tanh gate   [B][C][T][H][W]
__device__ float g_F[NELEM];                // sigmoid gate[B][C][T][H][W]
__device__ uint4 g_x[NPIX];                 // input fp16: pixel = 8 ci (4 fp16x2)
__device__ unsigned g_wfrag[4*14*4*32*4];   // fp16 weight fragments (2 nt / uint4)

// cp.async 16B with zero-fill when pred==false (src-size=0 -> no global read)
__device__ __forceinline__ void cp16(unsigned* sdst, const void* gsrc, bool pred) {
    unsigned saddr = (unsigned)__cvta_generic_to_shared(sdst);
    int sb = pred ? 16 : 0;
    asm volatile("cp.async.cg.shared.global [%0], [%1], 16, %2;\n"
                 :: "r"(saddr), "l"(gsrc), "r"(sb) : "memory");
}

// ---------------------------------------------------------------------------
// Input prep: fp32 -> fp16x2, pixel = 8 ci packed into one uint4.
// ---------------------------------------------------------------------------
__global__ void xsplit_kernel(const float* __restrict__ in) {
    int idx = blockIdx.x * 256 + threadIdx.x;
    if (idx >= NPIX) return;
    int w = idx % W_; int r = idx / W_;
    int h = r % H_;   r /= H_;
    int t = r % T_;   r /= T_;
    int cig = r & 3;  int b = r >> 2;
    size_t base = ((size_t)((b*CIN + cig*8)*T_ + t)*H_ + h)*W_ + w;
    unsigned wds[4];
    #pragma unroll
    for (int j = 0; j < 4; j++) {
        __half h0 = __float2half_rn(in[base + (size_t)(2*j)*CTHW]);
        __half h1 = __float2half_rn(in[base + (size_t)(2*j+1)*CTHW]);
        wds[j] = (unsigned)__half_as_ushort(h0) | ((unsigned)__half_as_ushort(h1) << 16);
    }
    g_x[idx] = make_uint4(wds[0], wds[1], wds[2], wds[3]);
}

// ---------------------------------------------------------------------------
// Weight fragment prep (fp16). word idx = cig*7168 + s*512 + ntp*128 + lane*4 + j
// ---------------------------------------------------------------------------
__global__ void wfrag_kernel(const float* __restrict__ w) {
    int idx = blockIdx.x * 256 + threadIdx.x;
    if (idx >= 4*7168) return;
    int j    = idx & 3;
    int lane = (idx >> 2) & 31;
    int ntp  = (idx >> 7) & 3;
    int rest = idx >> 9;
    int s    = rest % 14;
    int cig  = rest / 14;
    int nt = ntp*2 + (j >> 1);
    int r  = j & 1;
    int q  = lane & 3;
    int n  = nt*8 + (lane >> 2);    // co
    unsigned word = 0;
    for (int e = 0; e < 2; e++) {
        int k   = s*16 + q*2 + r*8 + e;
        int cil = k & 7;
        int tap = k >> 3;
        float val = 0.f;
        if (tap < 27) val = w[(n*CIN + (cig*8 + cil))*27 + tap];
        word |= ((unsigned)__half_as_ushort(__float2half_rn(val))) << (16*e);
    }
    g_wfrag[idx] = word;
}

// ---------------------------------------------------------------------------
__device__ __forceinline__ void mma16816(float (&c)[4], const unsigned (&a)[4],
                                         const unsigned b0, const unsigned b1) {
    asm volatile(
        "mma.sync.aligned.m16n8k16.row.col.f32.f16.f16.f32 "
        "{%0,%1,%2,%3}, {%4,%5,%6,%7}, {%8,%9}, {%0,%1,%2,%3};\n"
        : "+f"(c[0]), "+f"(c[1]), "+f"(c[2]), "+f"(c[3])
        : "r"(a[0]), "r"(a[1]), "r"(a[2]), "r"(a[3]), "r"(b0), "r"(b1));
}

// ---------------------------------------------------------------------------
// Conv3d 3x3x3 SAME + bias + tanh/sigmoid via implicit-GEMM HMMA (fp16, fp32
// accumulate), double-buffered cp.async pipeline. UNCHANGED from R8.
// ---------------------------------------------------------------------------
#define SX_WORDS (3*10*34*4)        /* 4080 words */
#define SWF_WORDS 7168
#define STAGE_WORDS (SX_WORDS + SWF_WORDS)
#define CONV_SMEM (2*STAGE_WORDS*4) /* 89,984 bytes */

__global__ __launch_bounds__(256, 2)
void conv_kernel(const float* __restrict__ bias) {
    extern __shared__ unsigned smw[];

    const int w0 = blockIdx.x * 32;
    const int h0 = blockIdx.y * 8;
    const int bz = blockIdx.z;
    const int b  = bz / T_;
    const int t  = bz % T_;
    const int tid  = threadIdx.x;
    const int lane = tid & 31;
    const int wi   = tid >> 5;      // warp -> output row
    const int g2   = lane >> 2;     // m-row within tile
    const int q2   = lane & 3;      // k / n low bits

    float acc[2][8][4];
    #pragma unroll
    for (int a2 = 0; a2 < 2; a2++)
        #pragma unroll
        for (int nt = 0; nt < 8; nt++)
            #pragma unroll
            for (int r = 0; r < 4; r++) acc[a2][nt][r] = 0.f;

    auto issue_load = [&](int cig, unsigned* s_x, unsigned* s_wf) {
        #pragma unroll
        for (int e0 = 0; e0 < 4; e0++) {
            int e = tid + e0*256;
            if (e < 1020) {
                int x  = e % 34; int r2 = e / 34;
                int y  = r2 % 10; int tz = r2 / 10;
                int tt = t + tz - 1, gh = h0 + y - 1, gw = w0 + x - 1;
                bool ok = (tt >= 0) & (tt < T_) & (gh >= 0) & (gh < H_) &
                          (gw >= 0) & (gw < W_);
                size_t gi = ok ? (((size_t)((b*4 + cig)*T_ + tt)*H_ + gh)*W_ + gw) : 0;
                cp16(s_x + e*4, g_x + gi, ok);
            }
        }
        const uint4* src = (const uint4*)(g_wfrag + cig*SWF_WORDS);
        #pragma unroll
        for (int li0 = 0; li0 < 7; li0++) {
            int li = tid + li0*256;
            cp16(s_wf + li*4, src + li, true);
        }
        asm volatile("cp.async.commit_group;\n" ::: "memory");
    };

    issue_load(0, smw, smw + SX_WORDS);

    for (int cig = 0; cig < 4; cig++) {
        unsigned* s_x  = smw + (cig & 1)*STAGE_WORDS;
        unsigned* s_wf = s_x + SX_WORDS;
        if (cig < 3) {
            unsigned* n_x = smw + ((cig + 1) & 1)*STAGE_WORDS;
            issue_load(cig + 1, n_x, n_x + SX_WORDS);
            asm volatile("cp.async.wait_group 1;\n" ::: "memory");
        } else {
            asm volatile("cp.async.wait_group 0;\n" ::: "memory");
        }
        __syncthreads();

        #pragma unroll
        for (int s = 0; s < 14; s++) {
            const int tapA = 2*s, tapB = 2*s + 1;
            const int ktA = tapA/9, rA = tapA%9, khA = rA/3, kwA = rA%3;
            const bool zB = (tapB == 27);
            const int ktB = zB ? 0 : tapB/9;
            const int rB  = zB ? 0 : tapB%9;
            const int khB = rB/3, kwB = rB%3;
            const int yA = wi + khA, yB = wi + khB;

            unsigned A[2][4];
            #pragma unroll
            for (int a2 = 0; a2 < 2; a2++) {
                const int xb = a2*16 + g2;
                const int iA0 = (((ktA*10 + yA)*34 + xb + kwA)*4) + q2;
                A[a2][0] = s_x[iA0];
                A[a2][1] = s_x[iA0 + 32];           /* +8 pixels */
                if (!zB) {
                    const int iB0 = (((ktB*10 + yB)*34 + xb + kwB)*4) + q2;
                    A[a2][2] = s_x[iB0];
                    A[a2][3] = s_x[iB0 + 32];       /* +8 pixels */
                } else {
                    A[a2][2] = 0u; A[a2][3] = 0u;
                }
            }
            #pragma unroll
            for (int ntp = 0; ntp < 4; ntp++) {
                uint4 B4 = *(const uint4*)(s_wf + (s*4 + ntp)*128 + lane*4);
                mma16816(acc[0][2*ntp],   A[0], B4.x, B4.y);
                mma16816(acc[1][2*ntp],   A[1], B4.x, B4.y);
                mma16816(acc[0][2*ntp+1], A[0], B4.z, B4.w);
                mma16816(acc[1][2*ntp+1], A[1], B4.z, B4.w);
            }
        }
        __syncthreads();
    }

    const int h = h0 + wi;
    #pragma unroll
    for (int a2 = 0; a2 < 2; a2++) {
        const int wbase = w0 + a2*16 + g2;
        #pragma unroll
        for (int nt = 0; nt < 8; nt++) {
            const int co = nt*8 + q2*2;
            const float b0v = __ldg(bias + co), b1v = __ldg(bias + co + 1);
            float x00 = acc[a2][nt][0] + b0v;
            float x01 = acc[a2][nt][1] + b1v;
            float x10 = acc[a2][nt][2] + b0v;
            float x11 = acc[a2][nt][3] + b1v;
            float y00, y01, y10, y11;
            float* dst; int c_;
            if (nt < 4) {
                y00 = tanhf(x00); y01 = tanhf(x01); y10 = tanhf(x10); y11 = tanhf(x11);
                dst = g_Z; c_ = co;
            } else {
                y00 = 1.f/(1.f + __expf(-x00)); y01 = 1.f/(1.f + __expf(-x01));
                y10 = 1.f/(1.f + __expf(-x10)); y11 = 1.f/(1.f + __expf(-x11));
                dst = g_F; c_ = co - HID;
            }
            size_t base0 = ((size_t)((b*HID + c_)*T_ + t)*H_ + h)*W_ + wbase;
            dst[base0]     = y00; dst[base0 + 8] = y10;
            size_t base1 = base0 + CTHW;
            dst[base1]     = y01; dst[base1 + 8] = y11;
        }
    }
}

// ---------------------------------------------------------------------------
// Fused recurrence + channel attention via HMMA.
// Block: 256 thr = 8 warps = 8 pixels (one pixel per warp).
// Per-pixel smem buffer (PXW=2308 words, 4-word skew between pixels):
//   [0,576)    Qhi  fp16 [c][t]  rows of 18 words (16 t-pairs + 2 pad)
//   [576,1152) Qlo  fp16 [c][t]
//   [1152,1728) QT  fp16 [t][d]  (hi only; row 31 zeroed)
//   [1728,2304) attnW fp16 [c][d] = attn[c,d]  (TRANSPOSED store of the
//               row-softmax fragments: reference softmax is over the ROW
//               axis c per column d; by Gram symmetry attn = rowSoftmax^T)
//   out fp32 [c*31+t] overlays [1152,2144) after the ah MMA.
// Scores S=QQ^T: 3 split passes (hi.hi + hi.lo + lo.hi), fp32 accum.
// ah^T = QT . attnW^T via mma row.col (A=QT[t][d], B=attnW[c][d]).
// ---------------------------------------------------------------------------
#define PXW     2308
#define OFF_QHI 0
#define OFF_QLO 576
#define OFF_QT  1152
#define OFF_AW  1728
#define OFF_OUT 1152
#define ATTN_SMEM (8*PXW*4)   /* 73,856 B -> 3 blocks/SM */

__global__ __launch_bounds__(256, 3)
void attn_kernel(const float* __restrict__ gamma, float* __restrict__ out) {
    extern __shared__ unsigned sm[];
    const int w0 = blockIdx.x * 8;
    const int h  = blockIdx.y;
    const int b  = blockIdx.z;
    const int tid = threadIdx.x;

    // ---- phase 1: recurrence -> Qhi/Qlo [c][t] + QT [t][c] ----
    {
        const int px = tid & 7;
        const int c  = tid >> 3;
        unsigned* qhi = sm + px*PXW + OFF_QHI + c*18;
        unsigned* qlo = sm + px*PXW + OFF_QLO + c*18;
        __half*   qt  = (__half*)(sm + px*PXW + OFF_QT);
        size_t base = (size_t)((b*HID + c)*T_)*HW + (size_t)h*W_ + w0 + px;
        float hs = 0.f;
        #pragma unroll
        for (int tp = 0; tp < 16; tp++) {
            __half hh[2], ll[2];
            #pragma unroll
            for (int e = 0; e < 2; e++) {
                int t = 2*tp + e;
                if (t < 31) {
                    float z = g_Z[base + (size_t)t*HW];
                    float f = g_F[base + (size_t)t*HW];
                    hs = f*hs + (1.f - f)*z;
                    hh[e] = __float2half_rn(hs);
                    ll[e] = __float2half_rn(hs - __half2float(hh[e]));
                } else {
                    hh[e] = __ushort_as_half((unsigned short)0);
                    ll[e] = __ushort_as_half((unsigned short)0);
                }
                qt[t*36 + c] = hh[e];
            }
            qhi[tp] = (unsigned)__half_as_ushort(hh[0]) |
                      ((unsigned)__half_as_ushort(hh[1]) << 16);
            qlo[tp] = (unsigned)__half_as_ushort(ll[0]) |
                      ((unsigned)__half_as_ushort(ll[1]) << 16);
        }
    }
    __syncthreads();

    // ---- phase 2: warp = pixel, HMMA ----
    const float gam = __ldg(gamma);
    const int lane = tid & 31;
    const int g2 = lane >> 2, q2 = lane & 3;
    unsigned* pxb = sm + (tid >> 5)*PXW;

    float acc[2][4][4];
    #pragma unroll
    for (int mt = 0; mt < 2; mt++)
        #pragma unroll
        for (int nt = 0; nt < 4; nt++)
            #pragma unroll
            for (int r = 0; r < 4; r++) acc[mt][nt][r] = 0.f;

    // scores: passes (Ahi,Bhi), (Ahi,Blo), (Alo,Bhi)
    #pragma unroll
    for (int p = 0; p < 3; p++) {
        const unsigned* Aa = pxb + ((p == 2) ? OFF_QLO : OFF_QHI);
        const unsigned* Bb = pxb + ((p == 1) ? OFF_QLO : OFF_QHI);
        #pragma unroll
        for (int kt = 0; kt < 2; kt++) {
            unsigned a[2][4];
            #pragma unroll
            for (int mt = 0; mt < 2; mt++) {
                int rb = (mt*16 + g2)*18 + kt*8 + q2;
                a[mt][0] = Aa[rb];
                a[mt][1] = Aa[rb + 144];   /* +8 rows */
                a[mt][2] = Aa[rb + 4];
                a[mt][3] = Aa[rb + 148];
            }
            #pragma unroll
            for (int nt = 0; nt < 4; nt++) {
                int bb = (nt*8 + g2)*18 + kt*8 + q2;
                unsigned b0 = Bb[bb], b1 = Bb[bb + 4];
                mma16816(acc[0][nt], a[0], b0, b1);
                mma16816(acc[1][nt], a[1], b0, b1);
            }
        }
    }

    // softmax: row stats (over d for fixed row c'), x 1/sqrt(32).
    // Thread holds rowSoftmax[c',d']; reference attn[c,d] = rowSoftmax[d,c]
    // (Gram symmetry), so store TRANSPOSED: AW[d'][c'] <- value.
    __half* AWh = (__half*)(pxb + OFF_AW);
    #pragma unroll
    for (int mt = 0; mt < 2; mt++) {
        #pragma unroll
        for (int rr = 0; rr < 2; rr++) {
            float m = -1e30f;
            #pragma unroll
            for (int nt = 0; nt < 4; nt++)
                m = fmaxf(m, fmaxf(acc[mt][nt][rr*2], acc[mt][nt][rr*2+1]));
            m = fmaxf(m, __shfl_xor_sync(0xffffffffu, m, 1));
            m = fmaxf(m, __shfl_xor_sync(0xffffffffu, m, 2));
            float s = 0.f;
            #pragma unroll
            for (int nt = 0; nt < 4; nt++) {
                float e0 = __expf(acc[mt][nt][rr*2]   - m);
                float e1 = __expf(acc[mt][nt][rr*2+1] - m);
                acc[mt][nt][rr*2] = e0; acc[mt][nt][rr*2+1] = e1;
                s += e0 + e1;
            }
            s += __shfl_xor_sync(0xffffffffu, s, 1);
            s += __shfl_xor_sync(0xffffffffu, s, 2);
            float inv = 0.17677669529663687f / s;
            const int cR = mt*16 + rr*8 + g2;          // row c' this thread owns
            #pragma unroll
            for (int nt = 0; nt < 4; nt++)
                #pragma unroll
                for (int e = 0; e < 2; e++) {
                    int dC = nt*8 + q2*2 + e;          // column d'
                    AWh[dC*36 + cR] =
                        __float2half_rn(acc[mt][nt][rr*2+e] * inv);
                }
        }
    }
    __syncwarp();

    // ah^T = QT . attnW^T  (A = QT[t][d], B = AW[c][d] = attn[c,d])
    float oacc[2][4][4];
    #pragma unroll
    for (int mt = 0; mt < 2; mt++)
        #pragma unroll
        for (int nt = 0; nt < 4; nt++)
            #pragma unroll
            for (int r = 0; r < 4; r++) oacc[mt][nt][r] = 0.f;

    {
        const unsigned* QT = pxb + OFF_QT;
        const unsigned* AW = pxb + OFF_AW;
        #pragma unroll
        for (int kt = 0; kt < 2; kt++) {
            unsigned a[2][4];
            #pragma unroll
            for (int mt = 0; mt < 2; mt++) {
                int rb = (mt*16 + g2)*18 + kt*8 + q2;
                a[mt][0] = QT[rb];
                a[mt][1] = QT[rb + 144];
                a[mt][2] = QT[rb + 4];
                a[mt][3] = QT[rb + 148];
            }
            #pragma unroll
            for (int nt = 0; nt < 4; nt++) {
                int bb = (nt*8 + g2)*18 + kt*8 + q2;
                unsigned b0 = AW[bb], b1 = AW[bb + 4];
                mma16816(oacc[0][nt], a[0], b0, b1);
                mma16816(oacc[1][nt], a[1], b0, b1);
            }
        }
    }

    // writeback: out = gamma*ah + (Qhi+Qlo), into fp32 out_s (overlays QT/AW)
    {
        const __half* qhiH = (const __half*)(pxb + OFF_QHI);
        const __half* qloH = (const __half*)(pxb + OFF_QLO);
        float* outs = (float*)(pxb + OFF_OUT);
        #pragma unroll
        for (int mt = 0; mt < 2; mt++)
            #pragma unroll
            for (int rr = 0; rr < 2; rr++) {
                int t = mt*16 + rr*8 + g2;
                if (t < 31) {
                    #pragma unroll
                    for (int nt = 0; nt < 4; nt++)
                        #pragma unroll
                        for (int e = 0; e < 2; e++) {
                            int c = nt*8 + q2*2 + e;
                            float hv = __half2float(qhiH[c*36 + t]) +
                                       __half2float(qloH[c*36 + t]);
                            outs[c*31 + t] = fmaf(gam, oacc[mt][nt][rr*2+e], hv);
                        }
                }
            }
    }
    __syncthreads();

    // ---- phase 3: coalesced store to [B][C][T][H][W] ----
    for (int i = tid; i < 8*992; i += 256) {
        int px = i & 7;
        int ct = i >> 3;
        int c  = ct / 31;
        int t2 = ct - c*31;
        out[((size_t)((b*HID + c)*T_ + t2)*H_ + h)*W_ + w0 + px] =
            ((const float*)(sm + px*PXW + OFF_OUT))[c*31 + t2];
    }
}

// ---------------------------------------------------------------------------
extern "C" void kernel_launch(void* const* d_in, const int* in_sizes, int n_in,
                              void* d_out, int out_size) {
    const float* input  = (const float*)d_in[0];
    const float* conv_w = (const float*)d_in[1];
    const float* conv_b = (const float*)d_in[2];
    const float* gamma  = (const float*)d_in[3];
    float* out = (float*)d_out;

    xsplit_kernel<<<(NPIX + 255)/256, 256>>>(input);           // our idx 0
    wfrag_kernel<<<(4*7168 + 255)/256, 256>>>(conv_w);         // our idx 1

    cudaFuncSetAttribute(conv_kernel, cudaFuncAttributeMaxDynamicSharedMemorySize,
                         CONV_SMEM);
    dim3 cgrid(W_/32, H_/8, B_*T_);
    conv_kernel<<<cgrid, 256, CONV_SMEM>>>(conv_b);            // our idx 2

    cudaFuncSetAttribute(attn_kernel, cudaFuncAttributeMaxDynamicSharedMemorySize,
                         ATTN_SMEM);
    dim3 agrid(W_/8, H_, B_);
    attn_kernel<<<agrid, 256, ATTN_SMEM>>>(gamma, out);        // our idx 3 -> ncu
}

// round 13
// speedup vs baseline: 1.2855x; 1.1462x over previous
#include <cuda_runtime.h>
#include <cuda_fp16.h>
#include <math.h>

#define B_   4
#define CIN  32
#define HID  32
#define T_   31
#define H_   96
#define W_   96
#define HW   (H_*W_)          /* 9216 */
#define CTHW ((size_t)T_*HW)  /* per-channel stride 285696 */
#define NELEM (B_*HID*T_*HW)
#define NPIX  (B_*4*T_*H_*W_) /* b,cig,t,h,w = 4,571,136 */

// Scratch (device globals; no runtime allocation)
__device__ unsigned g_ZF[NELEM];            // packed gates: half2(z, f) [B][C][T][H][W]
__device__ uint4 g_x[NPIX];                 // input fp16: pixel = 8 ci (4 fp16x2)
__device__ unsigned g_wfrag[4*14*4*32*4];   // fp16 weight fragments (2 nt / uint4)

// cp.async 16B with zero-fill when pred==false (src-size=0 -> no global read)
__device__ __forceinline__ void cp16(unsigned* sdst, const void* gsrc, bool pred) {
    unsigned saddr = (unsigned)__cvta_generic_to_shared(sdst);
    int sb = pred ? 16 : 0;
    asm volatile("cp.async.cg.shared.global [%0], [%1], 16, %2;\n"
                 :: "r"(saddr), "l"(gsrc), "r"(sb) : "memory");
}

// ---------------------------------------------------------------------------
// Input prep: fp32 -> fp16x2, pixel = 8 ci packed into one uint4.
// ---------------------------------------------------------------------------
__global__ void xsplit_kernel(const float* __restrict__ in) {
    int idx = blockIdx.x * 256 + threadIdx.x;
    if (idx >= NPIX) return;
    int w = idx % W_; int r = idx / W_;
    int h = r % H_;   r /= H_;
    int t = r % T_;   r /= T_;
    int cig = r & 3;  int b = r >> 2;
    size_t base = ((size_t)((b*CIN + cig*8)*T_ + t)*H_ + h)*W_ + w;
    unsigned wds[4];
    #pragma unroll
    for (int j = 0; j < 4; j++) {
        __half h0 = __float2half_rn(in[base + (size_t)(2*j)*CTHW]);
        __half h1 = __float2half_rn(in[base + (size_t)(2*j+1)*CTHW]);
        wds[j] = (unsigned)__half_as_ushort(h0) | ((unsigned)__half_as_ushort(h1) << 16);
    }
    g_x[idx] = make_uint4(wds[0], wds[1], wds[2], wds[3]);
}

// ---------------------------------------------------------------------------
// Weight fragment prep (fp16). word idx = cig*7168 + s*512 + ntp*128 + lane*4 + j
// ---------------------------------------------------------------------------
__global__ void wfrag_kernel(const float* __restrict__ w) {
    int idx = blockIdx.x * 256 + threadIdx.x;
    if (idx >= 4*7168) return;
    int j    = idx & 3;
    int lane = (idx >> 2) & 31;
    int ntp  = (idx >> 7) & 3;
    int rest = idx >> 9;
    int s    = rest % 14;
    int cig  = rest / 14;
    int nt = ntp*2 + (j >> 1);
    int r  = j & 1;
    int q  = lane & 3;
    int n  = nt*8 + (lane >> 2);    // co
    unsigned word = 0;
    for (int e = 0; e < 2; e++) {
        int k   = s*16 + q*2 + r*8 + e;
        int cil = k & 7;
        int tap = k >> 3;
        float val = 0.f;
        if (tap < 27) val = w[(n*CIN + (cig*8 + cil))*27 + tap];
        word |= ((unsigned)__half_as_ushort(__float2half_rn(val))) << (16*e);
    }
    g_wfrag[idx] = word;
}

// ---------------------------------------------------------------------------
__device__ __forceinline__ void mma16816(float (&c)[4], const unsigned (&a)[4],
                                         const unsigned b0, const unsigned b1) {
    asm volatile(
        "mma.sync.aligned.m16n8k16.row.col.f32.f16.f16.f32 "
        "{%0,%1,%2,%3}, {%4,%5,%6,%7}, {%8,%9}, {%0,%1,%2,%3};\n"
        : "+f"(c[0]), "+f"(c[1]), "+f"(c[2]), "+f"(c[3])
        : "r"(a[0]), "r"(a[1]), "r"(a[2]), "r"(a[3]), "r"(b0), "r"(b1));
}

// ---------------------------------------------------------------------------
// Conv3d 3x3x3 SAME + bias + tanh/sigmoid via implicit-GEMM HMMA (fp16, fp32
// accumulate), double-buffered cp.async pipeline. Epilogue now packs both
// gates of channel c into one half2 store (thread holds Z acc nt and F acc
// nt+4 for the same c).
// ---------------------------------------------------------------------------
#define SX_WORDS (3*10*34*4)        /* 4080 words */
#define SWF_WORDS 7168
#define STAGE_WORDS (SX_WORDS + SWF_WORDS)
#define CONV_SMEM (2*STAGE_WORDS*4) /* 89,984 bytes */

__global__ __launch_bounds__(256, 2)
void conv_kernel(const float* __restrict__ bias) {
    extern __shared__ unsigned smw[];

    const int w0 = blockIdx.x * 32;
    const int h0 = blockIdx.y * 8;
    const int bz = blockIdx.z;
    const int b  = bz / T_;
    const int t  = bz % T_;
    const int tid  = threadIdx.x;
    const int lane = tid & 31;
    const int wi   = tid >> 5;      // warp -> output row
    const int g2   = lane >> 2;     // m-row within tile
    const int q2   = lane & 3;      // k / n low bits

    float acc[2][8][4];
    #pragma unroll
    for (int a2 = 0; a2 < 2; a2++)
        #pragma unroll
        for (int nt = 0; nt < 8; nt++)
            #pragma unroll
            for (int r = 0; r < 4; r++) acc[a2][nt][r] = 0.f;

    auto issue_load = [&](int cig, unsigned* s_x, unsigned* s_wf) {
        #pragma unroll
        for (int e0 = 0; e0 < 4; e0++) {
            int e = tid + e0*256;
            if (e < 1020) {
                int x  = e % 34; int r2 = e / 34;
                int y  = r2 % 10; int tz = r2 / 10;
                int tt = t + tz - 1, gh = h0 + y - 1, gw = w0 + x - 1;
                bool ok = (tt >= 0) & (tt < T_) & (gh >= 0) & (gh < H_) &
                          (gw >= 0) & (gw < W_);
                size_t gi = ok ? (((size_t)((b*4 + cig)*T_ + tt)*H_ + gh)*W_ + gw) : 0;
                cp16(s_x + e*4, g_x + gi, ok);
            }
        }
        const uint4* src = (const uint4*)(g_wfrag + cig*SWF_WORDS);
        #pragma unroll
        for (int li0 = 0; li0 < 7; li0++) {
            int li = tid + li0*256;
            cp16(s_wf + li*4, src + li, true);
        }
        asm volatile("cp.async.commit_group;\n" ::: "memory");
    };

    issue_load(0, smw, smw + SX_WORDS);

    for (int cig = 0; cig < 4; cig++) {
        unsigned* s_x  = smw + (cig & 1)*STAGE_WORDS;
        unsigned* s_wf = s_x + SX_WORDS;
        if (cig < 3) {
            unsigned* n_x = smw + ((cig + 1) & 1)*STAGE_WORDS;
            issue_load(cig + 1, n_x, n_x + SX_WORDS);
            asm volatile("cp.async.wait_group 1;\n" ::: "memory");
        } else {
            asm volatile("cp.async.wait_group 0;\n" ::: "memory");
        }
        __syncthreads();

        #pragma unroll
        for (int s = 0; s < 14; s++) {
            const int tapA = 2*s, tapB = 2*s + 1;
            const int ktA = tapA/9, rA = tapA%9, khA = rA/3, kwA = rA%3;
            const bool zB = (tapB == 27);
            const int ktB = zB ? 0 : tapB/9;
            const int rB  = zB ? 0 : tapB%9;
            const int khB = rB/3, kwB = rB%3;
            const int yA = wi + khA, yB = wi + khB;

            unsigned A[2][4];
            #pragma unroll
            for (int a2 = 0; a2 < 2; a2++) {
                const int xb = a2*16 + g2;
                const int iA0 = (((ktA*10 + yA)*34 + xb + kwA)*4) + q2;
                A[a2][0] = s_x[iA0];
                A[a2][1] = s_x[iA0 + 32];           /* +8 pixels */
                if (!zB) {
                    const int iB0 = (((ktB*10 + yB)*34 + xb + kwB)*4) + q2;
                    A[a2][2] = s_x[iB0];
                    A[a2][3] = s_x[iB0 + 32];       /* +8 pixels */
                } else {
                    A[a2][2] = 0u; A[a2][3] = 0u;
                }
            }
            #pragma unroll
            for (int ntp = 0; ntp < 4; ntp++) {
                uint4 B4 = *(const uint4*)(s_wf + (s*4 + ntp)*128 + lane*4);
                mma16816(acc[0][2*ntp],   A[0], B4.x, B4.y);
                mma16816(acc[1][2*ntp],   A[1], B4.x, B4.y);
                mma16816(acc[0][2*ntp+1], A[0], B4.z, B4.w);
                mma16816(acc[1][2*ntp+1], A[1], B4.z, B4.w);
            }
        }
        __syncthreads();
    }

    // ---- epilogue: bias + activation, packed half2(z, f) stores ----
    const int h = h0 + wi;
    #pragma unroll
    for (int a2 = 0; a2 < 2; a2++) {
        const int wbase = w0 + a2*16 + g2;
        #pragma unroll
        for (int nt = 0; nt < 4; nt++) {
            const int c = nt*8 + q2*2;
            const float bz0 = __ldg(bias + c),      bz1 = __ldg(bias + c + 1);
            const float bf0 = __ldg(bias + c + 32), bf1 = __ldg(bias + c + 33);
            float z00 = tanhf(acc[a2][nt][0] + bz0);
            float z01 = tanhf(acc[a2][nt][1] + bz1);
            float z10 = tanhf(acc[a2][nt][2] + bz0);
            float z11 = tanhf(acc[a2][nt][3] + bz1);
            float f00 = 1.f/(1.f + __expf(-(acc[a2][nt+4][0] + bf0)));
            float f01 = 1.f/(1.f + __expf(-(acc[a2][nt+4][1] + bf1)));
            float f10 = 1.f/(1.f + __expf(-(acc[a2][nt+4][2] + bf0)));
            float f11 = 1.f/(1.f + __expf(-(acc[a2][nt+4][3] + bf1)));
            __half2 p00 = __floats2half2_rn(z00, f00);
            __half2 p01 = __floats2half2_rn(z01, f01);
            __half2 p10 = __floats2half2_rn(z10, f10);
            __half2 p11 = __floats2half2_rn(z11, f11);
            size_t base0 = ((size_t)((b*HID + c)*T_ + t)*H_ + h)*W_ + wbase;
            g_ZF[base0]     = *(unsigned*)&p00;
            g_ZF[base0 + 8] = *(unsigned*)&p10;
            size_t base1 = base0 + CTHW;
            g_ZF[base1]     = *(unsigned*)&p01;
            g_ZF[base1 + 8] = *(unsigned*)&p11;
        }
    }
}

// ---------------------------------------------------------------------------
// Fused recurrence + channel attention via HMMA (R12 structure, packed gates).
// Block: 256 thr = 8 warps = 8 pixels (one pixel per warp).
// Per-pixel smem buffer (PXW=2308 words, 4-word skew between pixels):
//   [0,576)    Qhi  fp16 [c][t]  rows of 18 words (16 t-pairs + 2 pad)
//   [576,1152) Qlo  fp16 [c][t]
//   [1152,1728) QT  fp16 [t][d]  (hi only; row 31 zeroed)
//   [1728,2304) attnW fp16 [c][d] = attn[c,d] (transposed row-softmax)
//   out fp32 [c*31+t] overlays [1152,2144) after the ah MMA.
// ---------------------------------------------------------------------------
#define PXW     2308
#define OFF_QHI 0
#define OFF_QLO 576
#define OFF_QT  1152
#define OFF_AW  1728
#define OFF_OUT 1152
#define ATTN_SMEM (8*PXW*4)   /* 73,856 B -> 3 blocks/SM */

__global__ __launch_bounds__(256, 3)
void attn_kernel(const float* __restrict__ gamma, float* __restrict__ out) {
    extern __shared__ unsigned sm[];
    const int w0 = blockIdx.x * 8;
    const int h  = blockIdx.y;
    const int b  = blockIdx.z;
    const int tid = threadIdx.x;

    // ---- phase 1: recurrence (single packed load per step) ----
    {
        const int px = tid & 7;
        const int c  = tid >> 3;
        unsigned* qhi = sm + px*PXW + OFF_QHI + c*18;
        unsigned* qlo = sm + px*PXW + OFF_QLO + c*18;
        __half*   qt  = (__half*)(sm + px*PXW + OFF_QT);
        size_t base = (size_t)((b*HID + c)*T_)*HW + (size_t)h*W_ + w0 + px;
        float hs = 0.f;
        #pragma unroll
        for (int tp = 0; tp < 16; tp++) {
            __half hh[2], ll[2];
            #pragma unroll
            for (int e = 0; e < 2; e++) {
                int t = 2*tp + e;
                if (t < 31) {
                    unsigned v = g_ZF[base + (size_t)t*HW];
                    __half2 hv = *(__half2*)&v;
                    float z = __low2float(hv);
                    float f = __high2float(hv);
                    hs = f*hs + (1.f - f)*z;
                    hh[e] = __float2half_rn(hs);
                    ll[e] = __float2half_rn(hs - __half2float(hh[e]));
                } else {
                    hh[e] = __ushort_as_half((unsigned short)0);
                    ll[e] = __ushort_as_half((unsigned short)0);
                }
                qt[t*36 + c] = hh[e];
            }
            qhi[tp] = (unsigned)__half_as_ushort(hh[0]) |
                      ((unsigned)__half_as_ushort(hh[1]) << 16);
            qlo[tp] = (unsigned)__half_as_ushort(ll[0]) |
                      ((unsigned)__half_as_ushort(ll[1]) << 16);
        }
    }
    __syncthreads();

    // ---- phase 2: warp = pixel, HMMA ----
    const float gam = __ldg(gamma);
    const int lane = tid & 31;
    const int g2 = lane >> 2, q2 = lane & 3;
    unsigned* pxb = sm + (tid >> 5)*PXW;

    float acc[2][4][4];
    #pragma unroll
    for (int mt = 0; mt < 2; mt++)
        #pragma unroll
        for (int nt = 0; nt < 4; nt++)
            #pragma unroll
            for (int r = 0; r < 4; r++) acc[mt][nt][r] = 0.f;

    // scores: passes (Ahi,Bhi), (Ahi,Blo), (Alo,Bhi)
    #pragma unroll
    for (int p = 0; p < 3; p++) {
        const unsigned* Aa = pxb + ((p == 2) ? OFF_QLO : OFF_QHI);
        const unsigned* Bb = pxb + ((p == 1) ? OFF_QLO : OFF_QHI);
        #pragma unroll
        for (int kt = 0; kt < 2; kt++) {
            unsigned a[2][4];
            #pragma unroll
            for (int mt = 0; mt < 2; mt++) {
                int rb = (mt*16 + g2)*18 + kt*8 + q2;
                a[mt][0] = Aa[rb];
                a[mt][1] = Aa[rb + 144];   /* +8 rows */
                a[mt][2] = Aa[rb + 4];
                a[mt][3] = Aa[rb + 148];
            }
            #pragma unroll
            for (int nt = 0; nt < 4; nt++) {
                int bb = (nt*8 + g2)*18 + kt*8 + q2;
                unsigned b0 = Bb[bb], b1 = Bb[bb + 4];
                mma16816(acc[0][nt], a[0], b0, b1);
                mma16816(acc[1][nt], a[1], b0, b1);
            }
        }
    }

    // softmax: row stats, x 1/sqrt(32); store TRANSPOSED -> AW[d][c]
    __half* AWh = (__half*)(pxb + OFF_AW);
    #pragma unroll
    for (int mt = 0; mt < 2; mt++) {
        #pragma unroll
        for (int rr = 0; rr < 2; rr++) {
            float m = -1e30f;
            #pragma unroll
            for (int nt = 0; nt < 4; nt++)
                m = fmaxf(m, fmaxf(acc[mt][nt][rr*2], acc[mt][nt][rr*2+1]));
            m = fmaxf(m, __shfl_xor_sync(0xffffffffu, m, 1));
            m = fmaxf(m, __shfl_xor_sync(0xffffffffu, m, 2));
            float s = 0.f;
            #pragma unroll
            for (int nt = 0; nt < 4; nt++) {
                float e0 = __expf(acc[mt][nt][rr*2]   - m);
                float e1 = __expf(acc[mt][nt][rr*2+1] - m);
                acc[mt][nt][rr*2] = e0; acc[mt][nt][rr*2+1] = e1;
                s += e0 + e1;
            }
            s += __shfl_xor_sync(0xffffffffu, s, 1);
            s += __shfl_xor_sync(0xffffffffu, s, 2);
            float inv = 0.17677669529663687f / s;
            const int cR = mt*16 + rr*8 + g2;
            #pragma unroll
            for (int nt = 0; nt < 4; nt++)
                #pragma unroll
                for (int e = 0; e < 2; e++) {
                    int dC = nt*8 + q2*2 + e;
                    AWh[dC*36 + cR] =
                        __float2half_rn(acc[mt][nt][rr*2+e] * inv);
                }
        }
    }
    __syncwarp();

    // ah^T = QT . attnW^T  (A = QT[t][d], B = AW[c][d] = attn[c,d])
    float oacc[2][4][4];
    #pragma unroll
    for (int mt = 0; mt < 2; mt++)
        #pragma unroll
        for (int nt = 0; nt < 4; nt++)
            #pragma unroll
            for (int r = 0; r < 4; r++) oacc[mt][nt][r] = 0.f;

    {
        const unsigned* QT = pxb + OFF_QT;
        const unsigned* AW = pxb + OFF_AW;
        #pragma unroll
        for (int kt = 0; kt < 2; kt++) {
            unsigned a[2][4];
            #pragma unroll
            for (int mt = 0; mt < 2; mt++) {
                int rb = (mt*16 + g2)*18 + kt*8 + q2;
                a[mt][0] = QT[rb];
                a[mt][1] = QT[rb + 144];
                a[mt][2] = QT[rb + 4];
                a[mt][3] = QT[rb + 148];
            }
            #pragma unroll
            for (int nt = 0; nt < 4; nt++) {
                int bb = (nt*8 + g2)*18 + kt*8 + q2;
                unsigned b0 = AW[bb], b1 = AW[bb + 4];
                mma16816(oacc[0][nt], a[0], b0, b1);
                mma16816(oacc[1][nt], a[1], b0, b1);
            }
        }
    }

    // writeback: out = gamma*ah + (Qhi+Qlo), into fp32 out_s (overlays QT/AW)
    {
        const __half* qhiH = (const __half*)(pxb + OFF_QHI);
        const __half* qloH = (const __half*)(pxb + OFF_QLO);
        float* outs = (float*)(pxb + OFF_OUT);
        #pragma unroll
        for (int mt = 0; mt < 2; mt++)
            #pragma unroll
            for (int rr = 0; rr < 2; rr++) {
                int t = mt*16 + rr*8 + g2;
                if (t < 31) {
                    #pragma unroll
                    for (int nt = 0; nt < 4; nt++)
                        #pragma unroll
                        for (int e = 0; e < 2; e++) {
                            int c = nt*8 + q2*2 + e;
                            float hv = __half2float(qhiH[c*36 + t]) +
                                       __half2float(qloH[c*36 + t]);
                            outs[c*31 + t] = fmaf(gam, oacc[mt][nt][rr*2+e], hv);
                        }
                }
            }
    }
    __syncthreads();

    // ---- phase 3: coalesced store to [B][C][T][H][W] ----
    for (int i = tid; i < 8*992; i += 256) {
        int px = i & 7;
        int ct = i >> 3;
        int c  = ct / 31;
        int t2 = ct - c*31;
        out[((size_t)((b*HID + c)*T_ + t2)*H_ + h)*W_ + w0 + px] =
            ((const float*)(sm + px*PXW + OFF_OUT))[c*31 + t2];
    }
}

// ---------------------------------------------------------------------------
extern "C" void kernel_launch(void* const* d_in, const int* in_sizes, int n_in,
                              void* d_out, int out_size) {
    const float* input  = (const float*)d_in[0];
    const float* conv_w = (const float*)d_in[1];
    const float* conv_b = (const float*)d_in[2];
    const float* gamma  = (const float*)d_in[3];
    float* out = (float*)d_out;

    xsplit_kernel<<<(NPIX + 255)/256, 256>>>(input);           // our idx 0
    wfrag_kernel<<<(4*7168 + 255)/256, 256>>>(conv_w);         // our idx 1

    cudaFuncSetAttribute(conv_kernel, cudaFuncAttributeMaxDynamicSharedMemorySize,
                         CONV_SMEM);
    dim3 cgrid(W_/32, H_/8, B_*T_);
    conv_kernel<<<cgrid, 256, CONV_SMEM>>>(conv_b);            // our idx 2

    cudaFuncSetAttribute(attn_kernel, cudaFuncAttributeMaxDynamicSharedMemorySize,
                         ATTN_SMEM);
    dim3 agrid(W_/8, H_, B_);
    attn_kernel<<<agrid, 256, ATTN_SMEM>>>(gamma, out);        // our idx 3 -> ncu
}